// round 8
// baseline (speedup 1.0000x reference)
#include <cuda_runtime.h>
#include <math.h>

#define B_SEQ   2048
#define D_DIM   128
#define H_DIM   128
#define G3      384            // 3*H
#define MAX_LEN 200
#define MAX_T   (B_SEQ * (MAX_LEN - 1))
#define NSEQ    2              // sequences per GRU block

__device__ float g_xproj[(size_t)MAX_T * G3];
__device__ int      g_off[B_SEQ];
__device__ unsigned g_order[B_SEQ];

// packed fp32x2 FMA: d = a*b + d
__device__ __forceinline__ void ffma2(unsigned long long& d,
                                      unsigned long long a,
                                      unsigned long long b) {
    asm volatile("fma.rn.f32x2 %0, %1, %2, %0;" : "+l"(d) : "l"(a), "l"(b));
}
__device__ __forceinline__ float unpack_sum(unsigned long long v) {
    unsigned int lo, hi;
    asm("mov.b64 {%0,%1}, %2;" : "=r"(lo), "=r"(hi) : "l"(v));
    return __uint_as_float(lo) + __uint_as_float(hi);
}
__device__ __forceinline__ float fast_sigmoid(float x) {
    return __fdividef(1.f, 1.f + __expf(-x));
}
__device__ __forceinline__ float fast_tanh(float x) {
    x = fminf(fmaxf(x, -15.f), 15.f);
    float e2 = __expf(2.f * x);
    return __fdividef(e2 - 1.f, e2 + 1.f);
}

// ---------------------------------------------------------------------------
__global__ void offsets_kernel(const void* __restrict__ off_raw) {
    __shared__ int is64;
    const int* v32 = (const int*)off_raw;
    if (threadIdx.x == 0) {
        int f = 0;
        #pragma unroll
        for (int i = 0; i < 31; ++i)
            if (v32[i + 1] < v32[i]) f = 1;
        is64 = f;
    }
    __syncthreads();
    int gid = blockIdx.x * blockDim.x + threadIdx.x;
    if (gid < B_SEQ) {
        if (is64) {
            const long long* v64 = (const long long*)off_raw;
            g_off[gid] = (int)v64[gid];
        } else {
            g_off[gid] = v32[gid];
        }
    }
}

// ---------------------------------------------------------------------------
// Bitonic sort (length desc) for equal-length pairing + longest-first launch.
// ---------------------------------------------------------------------------
__global__ void sort_kernel(int T) {
    __shared__ unsigned key[B_SEQ];
    const int tid = threadIdx.x;
    for (int i = tid; i < B_SEQ; i += 1024) {
        int off = g_off[i];
        int end = (i == B_SEQ - 1) ? T : g_off[i + 1];
        key[i] = ((unsigned)(end - off) << 11) | (unsigned)i;
    }
    __syncthreads();
    for (int k = 2; k <= B_SEQ; k <<= 1) {
        for (int s = k >> 1; s > 0; s >>= 1) {
            for (int i = tid; i < B_SEQ; i += 1024) {
                int ixj = i ^ s;
                if (ixj > i) {
                    unsigned a = key[i], b = key[ixj];
                    bool seg_up = ((i & k) == 0);
                    if (seg_up ? (a < b) : (a > b)) { key[i] = b; key[ixj] = a; }
                }
            }
            __syncthreads();
        }
    }
    for (int i = tid; i < B_SEQ; i += 1024) g_order[i] = key[i] & 0x7FFu;
}

// ---------------------------------------------------------------------------
// Kernel 1: persistent x-projection.
// ---------------------------------------------------------------------------
#define XTILE 96
__global__ __launch_bounds__(384, 1)
void xproj_kernel(const float* __restrict__ x,
                  const float* __restrict__ W_ih, int T) {
    __shared__ __align__(16) float sx[XTILE * 128];
    const int j = threadIdx.x;

    unsigned long long w2[64];
    {
        const ulonglong2* wr =
            reinterpret_cast<const ulonglong2*>(W_ih + (size_t)j * 128);
        #pragma unroll
        for (int k = 0; k < 32; ++k) {
            ulonglong2 v = wr[k];
            w2[2*k]   = v.x;
            w2[2*k+1] = v.y;
        }
    }

    const int ntiles = (T + XTILE - 1) / XTILE;
    for (int tile = blockIdx.x; tile < ntiles; tile += gridDim.x) {
        const int t0 = tile * XTILE;
        const int ntok = min(XTILE, T - t0);

        __syncthreads();
        const float4* xg = reinterpret_cast<const float4*>(x + (size_t)t0 * D_DIM);
        float4* sx4 = reinterpret_cast<float4*>(sx);
        for (int i = j; i < ntok * 32; i += 384) sx4[i] = xg[i];
        __syncthreads();

        float* outp = g_xproj + (size_t)t0 * G3 + j;
        for (int t = 0; t < ntok; ++t) {
            const ulonglong2* hv =
                reinterpret_cast<const ulonglong2*>(sx + t * D_DIM);
            unsigned long long a0 = 0ull, a1 = 0ull, a2 = 0ull, a3 = 0ull;
            #pragma unroll
            for (int k = 0; k < 16; ++k) {
                ulonglong2 h0 = hv[2*k];
                ulonglong2 h1 = hv[2*k+1];
                ffma2(a0, w2[4*k+0], h0.x);
                ffma2(a1, w2[4*k+1], h0.y);
                ffma2(a2, w2[4*k+2], h1.x);
                ffma2(a3, w2[4*k+3], h1.y);
            }
            outp[(size_t)t * G3] =
                (unpack_sum(a0) + unpack_sum(a1)) + (unpack_sum(a2) + unpack_sum(a3));
        }
    }
}

// ---------------------------------------------------------------------------
// Kernel 2: ragged GRU, 2 seqs/block, SPLIT-K=4 register blocking.
// Thread j: k-slice ks=j&3 (32 k-values), rows rg*4+i (rg=j>>2, i=0..3).
// Each h-load feeds 4 FMAs -> 4x less smem crossbar traffic.
// Partials reduced across the 4 adjacent lanes via shfl_xor; thread j ends
// with hg for row j, preserving the R4 gate-phase structure exactly.
// ---------------------------------------------------------------------------
__global__ __launch_bounds__(384, 1)
void gru_kernel(const float* __restrict__ W_hh,
                const float* __restrict__ W_dense,
                const float* __restrict__ b_dense,
                float* __restrict__ out, int T) {
    const int j = threadIdx.x;
    const int ks = j & 3;
    const int rg = j >> 2;

    __shared__ __align__(16) float sh_h[NSEQ][128];
    __shared__ float sh_a[NSEQ][384];
    __shared__ float sh_hgn[NSEQ][128];
    __shared__ float sh_red[NSEQ][4];
    __shared__ float sh_inv[NSEQ];
    __shared__ int   sh_meta[NSEQ * 3];

    // weights: rows rg*4+i, k in [ks*32, ks*32+32)
    unsigned long long w2[4][16];
    #pragma unroll
    for (int i = 0; i < 4; ++i) {
        const ulonglong2* wr = reinterpret_cast<const ulonglong2*>(
            W_hh + (size_t)(rg * 4 + i) * 128 + ks * 32);
        #pragma unroll
        for (int k8 = 0; k8 < 8; ++k8) {
            ulonglong2 v = wr[k8];
            w2[i][2*k8]   = v.x;
            w2[i][2*k8+1] = v.y;
        }
    }

    if (j < NSEQ) {
        int sidx = (int)g_order[blockIdx.x * NSEQ + j];
        int off  = g_off[sidx];
        int end  = (sidx == B_SEQ - 1) ? T : g_off[sidx + 1];
        sh_meta[3*j]     = off;
        sh_meta[3*j + 1] = end - off;
        sh_meta[3*j + 2] = sidx;
    }
    if (j < 128) { sh_h[0][j] = 0.f; sh_h[1][j] = 0.f; }
    __syncthreads();

    const int off0 = sh_meta[0], len0 = sh_meta[1];
    const int off1 = sh_meta[3], len1 = sh_meta[4];
    const int maxlen = max(len0, len1);
    const int l0 = len0 - 1, l1 = len1 - 1;

    const float* xgp0 = g_xproj + (size_t)off0 * G3 + j;
    const float* xgp1 = g_xproj + (size_t)off1 * G3 + j;

    float xg0c = xgp0[0];
    float xg1c = xgp1[0];
    float xg0n = xgp0[(size_t)min(1, l0) * G3];
    float xg1n = xgp1[(size_t)min(1, l1) * G3];

    for (int t = 0; t < maxlen; ++t) {
        float xg0p = xgp0[(size_t)min(t + 2, l0) * G3];
        float xg1p = xgp1[(size_t)min(t + 2, l1) * G3];

        #pragma unroll
        for (int s = 0; s < NSEQ; ++s) {
            const ulonglong2* hv = reinterpret_cast<const ulonglong2*>(
                sh_h[s] + ks * 32);
            unsigned long long acc0 = 0ull, acc1 = 0ull,
                               acc2 = 0ull, acc3 = 0ull;
            #pragma unroll
            for (int k4 = 0; k4 < 4; ++k4) {
                ulonglong2 ha = hv[2*k4];
                ulonglong2 hb = hv[2*k4+1];
                ffma2(acc0, w2[0][4*k4+0], ha.x);
                ffma2(acc1, w2[1][4*k4+0], ha.x);
                ffma2(acc2, w2[2][4*k4+0], ha.x);
                ffma2(acc3, w2[3][4*k4+0], ha.x);
                ffma2(acc0, w2[0][4*k4+1], ha.y);
                ffma2(acc1, w2[1][4*k4+1], ha.y);
                ffma2(acc2, w2[2][4*k4+1], ha.y);
                ffma2(acc3, w2[3][4*k4+1], ha.y);
                ffma2(acc0, w2[0][4*k4+2], hb.x);
                ffma2(acc1, w2[1][4*k4+2], hb.x);
                ffma2(acc2, w2[2][4*k4+2], hb.x);
                ffma2(acc3, w2[3][4*k4+2], hb.x);
                ffma2(acc0, w2[0][4*k4+3], hb.y);
                ffma2(acc1, w2[1][4*k4+3], hb.y);
                ffma2(acc2, w2[2][4*k4+3], hb.y);
                ffma2(acc3, w2[3][4*k4+3], hb.y);
            }
            float p0 = unpack_sum(acc0);
            float p1 = unpack_sum(acc1);
            float p2 = unpack_sum(acc2);
            float p3 = unpack_sum(acc3);
            // butterfly over the 4-lane k-slice group
            p0 += __shfl_xor_sync(0xffffffffu, p0, 1);
            p1 += __shfl_xor_sync(0xffffffffu, p1, 1);
            p2 += __shfl_xor_sync(0xffffffffu, p2, 1);
            p3 += __shfl_xor_sync(0xffffffffu, p3, 1);
            p0 += __shfl_xor_sync(0xffffffffu, p0, 2);
            p1 += __shfl_xor_sync(0xffffffffu, p1, 2);
            p2 += __shfl_xor_sync(0xffffffffu, p2, 2);
            p3 += __shfl_xor_sync(0xffffffffu, p3, 2);
            // thread j's row is exactly j = rg*4 + ks
            float hg = (ks == 0) ? p0 : (ks == 1) ? p1 : (ks == 2) ? p2 : p3;
            float xg = s ? xg1c : xg0c;
            sh_a[s][j] = xg + hg;
            if (j >= 256) sh_hgn[s][j - 256] = hg;
        }
        __syncthreads();

        if (j < 256) {
            const int s    = j >> 7;
            const int lane = j & 127;
            const int len_s = s ? len1 : len0;
            if (t < len_s) {
                const float* a = sh_a[s];
                float r = fast_sigmoid(a[lane]);
                float z = fast_sigmoid(a[lane + 128]);
                float n = fast_tanh(a[lane + 256] + (r - 1.f) * sh_hgn[s][lane]);
                sh_h[s][lane] = (1.f - z) * n + z * sh_h[s][lane];
            }
        }
        __syncthreads();

        xg0c = xg0n; xg0n = xg0p;
        xg1c = xg1n; xg1n = xg1p;
    }

    // ---- epilogue: dense + L2-normalize ----
    float v = 0.f;
    int s = 0, lane = 0;
    if (j < 256) {
        s = j >> 7; lane = j & 127;
        const ulonglong2* wd =
            reinterpret_cast<const ulonglong2*>(W_dense + (size_t)lane * 128);
        const ulonglong2* hv = reinterpret_cast<const ulonglong2*>(sh_h[s]);
        unsigned long long a0 = 0ull, a1 = 0ull;
        #pragma unroll
        for (int k = 0; k < 16; ++k) {
            ulonglong2 wv = wd[2*k];
            ulonglong2 wu = wd[2*k+1];
            ulonglong2 h0 = hv[2*k];
            ulonglong2 h1 = hv[2*k+1];
            ffma2(a0, wv.x, h0.x);
            ffma2(a1, wv.y, h0.y);
            ffma2(a0, wu.x, h1.x);
            ffma2(a1, wu.y, h1.y);
        }
        v = unpack_sum(a0) + unpack_sum(a1) + b_dense[lane];
        float sq = v * v;
        #pragma unroll
        for (int d = 16; d > 0; d >>= 1)
            sq += __shfl_xor_sync(0xffffffffu, sq, d);
        if ((lane & 31) == 0) sh_red[s][lane >> 5] = sq;
    }
    __syncthreads();
    if (j < NSEQ) {
        float ss = sh_red[j][0] + sh_red[j][1] + sh_red[j][2] + sh_red[j][3];
        sh_inv[j] = 1.f / fmaxf(sqrtf(ss), 1e-12f);
    }
    __syncthreads();
    if (j < 256) {
        const int sidx = sh_meta[3*s + 2];
        out[(size_t)sidx * D_DIM + lane] = v * sh_inv[s];
    }
}

// ---------------------------------------------------------------------------
extern "C" void kernel_launch(void* const* d_in, const int* in_sizes, int n_in,
                              void* d_out, int out_size) {
    const float* x       = (const float*)d_in[0];
    const void*  off_raw = d_in[1];
    const float* W_ih    = (const float*)d_in[2];
    const float* W_hh    = (const float*)d_in[3];
    const float* W_dense = (const float*)d_in[4];
    const float* b_dense = (const float*)d_in[5];
    float* out = (float*)d_out;

    const int T = in_sizes[0] / D_DIM;

    offsets_kernel<<<2, 1024>>>(off_raw);
    sort_kernel<<<1, 1024>>>(T);

    xproj_kernel<<<148, 384>>>(x, W_ih, T);

    gru_kernel<<<B_SEQ / NSEQ, 384>>>(W_hh, W_dense, b_dense, out, T);
}